// round 10
// baseline (speedup 1.0000x reference)
#include <cuda_runtime.h>
#include <math.h>

// SE(3) exp + point transform, single kernel, NO block barrier.
// out[bt,n,:] = R(dofs[bt]) * X[bt,n,:] + t(dofs[bt])
// X_v: [B,T,N,3] f32, dofs: [B,T,6] f32, out: [B,T,N,3] f32. B=64,T=28,N=4096.
//
// One 256-thread block per bt slice (1792 blocks). Lane 0 of each warp
// computes R,t once, broadcast via __shfl_sync; each thread then runs 4
// strictly-sequential iterations of (3x float4 load -> 36 FMA -> 3x float4
// store). unroll 1 + no prefetch keeps MLP_p1=3 per iteration (the proven
// sweet spot) and regs ~40, while amortizing the ~57-slot per-warp prologue
// over 16 points/thread instead of 4.

#define THREADS 256
#define ITERS 4
#define TILES_PER_SLICE 1024    // N*3/12 = 4096*3/12

__global__ void __launch_bounds__(THREADS)
se3_transform_kernel(const float* __restrict__ X,
                     const float* __restrict__ dofs,
                     float* __restrict__ out)
{
    const unsigned bt = blockIdx.x;              // one block per (b,t) slice
    const int lane    = threadIdx.x & 31;

    // ---- warm the pipeline: issue iteration-0 loads FIRST ----
    const unsigned tile0 = bt * TILES_PER_SLICE + threadIdx.x;
    const float4* __restrict__ src0 =
        reinterpret_cast<const float4*>(X + (size_t)tile0 * 12);
    float4 va = __ldcs(&src0[0]);
    float4 vb = __ldcs(&src0[1]);
    float4 vc = __ldcs(&src0[2]);

    // ---- lane 0 computes R,t (hidden under load latency) ----
    float r00, r01, r02, r10, r11, r12, r20, r21, r22, t0, t1, t2;
    if (lane == 0) {
        const float* d = dofs + bt * 6;
        const float tx = __ldg(&d[0]), ty = __ldg(&d[1]), tz = __ldg(&d[2]);
        const float wx = __ldg(&d[3]), wy = __ldg(&d[4]), wz = __ldg(&d[5]);

        const float nrm   = wx*wx + wy*wy + wz*wz;
        const float th2c  = fmaxf(nrm, 1.0e-4f);   // clip BEFORE sqrt (matches ref)
        const float theta = sqrtf(th2c);
        float st, ct;
        sincosf(theta, &st, &ct);
        const float inv_t  = 1.0f / theta;
        const float inv_t2 = inv_t * inv_t;
        const float f1 = st * inv_t;
        const float f2 = (1.0f - ct) * inv_t2;
        const float f3 = (theta - st) * inv_t2 * inv_t;

        // H2 = H@H = w w^T - (w.w) I  (raw nrm, matches ref)
        const float h2xx = wx*wx - nrm, h2yy = wy*wy - nrm, h2zz = wz*wz - nrm;
        const float h2xy = wx*wy, h2xz = wx*wz, h2yz = wy*wz;

        r00 = 1.0f + f2*h2xx;
        r01 = -f1*wz + f2*h2xy;
        r02 =  f1*wy + f2*h2xz;
        r10 =  f1*wz + f2*h2xy;
        r11 = 1.0f + f2*h2yy;
        r12 = -f1*wx + f2*h2yz;
        r20 = -f1*wy + f2*h2xz;
        r21 =  f1*wx + f2*h2yz;
        r22 = 1.0f + f2*h2zz;

        const float v00 = 1.0f + f3*h2xx;
        const float v01 = -f2*wz + f3*h2xy;
        const float v02 =  f2*wy + f3*h2xz;
        const float v10 =  f2*wz + f3*h2xy;
        const float v11 = 1.0f + f3*h2yy;
        const float v12 = -f2*wx + f3*h2yz;
        const float v20 = -f2*wy + f3*h2xz;
        const float v21 =  f2*wx + f3*h2yz;
        const float v22 = 1.0f + f3*h2zz;

        t0 = v00*tx + v01*ty + v02*tz;
        t1 = v10*tx + v11*ty + v12*tz;
        t2 = v20*tx + v21*ty + v22*tz;
    }

    // ---- warp broadcast (no smem, no block barrier) ----
    r00 = __shfl_sync(0xffffffffu, r00, 0);
    r01 = __shfl_sync(0xffffffffu, r01, 0);
    r02 = __shfl_sync(0xffffffffu, r02, 0);
    r10 = __shfl_sync(0xffffffffu, r10, 0);
    r11 = __shfl_sync(0xffffffffu, r11, 0);
    r12 = __shfl_sync(0xffffffffu, r12, 0);
    r20 = __shfl_sync(0xffffffffu, r20, 0);
    r21 = __shfl_sync(0xffffffffu, r21, 0);
    r22 = __shfl_sync(0xffffffffu, r22, 0);
    t0  = __shfl_sync(0xffffffffu, t0, 0);
    t1  = __shfl_sync(0xffffffffu, t1, 0);
    t2  = __shfl_sync(0xffffffffu, t2, 0);

#pragma unroll 1
    for (int it = 0; it < ITERS; ++it) {
        const unsigned tile = tile0 + it * THREADS;
        const float4* __restrict__ src =
            reinterpret_cast<const float4*>(X + (size_t)tile * 12);
        float4* __restrict__ dst =
            reinterpret_cast<float4*>(out + (size_t)tile * 12);

        if (it != 0) {                // iter 0 already loaded before prologue
            va = __ldcs(&src[0]);
            vb = __ldcs(&src[1]);
            vc = __ldcs(&src[2]);
        }

        const float o0x = fmaf(r00, va.x, fmaf(r01, va.y, fmaf(r02, va.z, t0)));
        const float o0y = fmaf(r10, va.x, fmaf(r11, va.y, fmaf(r12, va.z, t1)));
        const float o0z = fmaf(r20, va.x, fmaf(r21, va.y, fmaf(r22, va.z, t2)));

        const float o1x = fmaf(r00, va.w, fmaf(r01, vb.x, fmaf(r02, vb.y, t0)));
        const float o1y = fmaf(r10, va.w, fmaf(r11, vb.x, fmaf(r12, vb.y, t1)));
        const float o1z = fmaf(r20, va.w, fmaf(r21, vb.x, fmaf(r22, vb.y, t2)));

        const float o2x = fmaf(r00, vb.z, fmaf(r01, vb.w, fmaf(r02, vc.x, t0)));
        const float o2y = fmaf(r10, vb.z, fmaf(r11, vb.w, fmaf(r12, vc.x, t1)));
        const float o2z = fmaf(r20, vb.z, fmaf(r21, vb.w, fmaf(r22, vc.x, t2)));

        const float o3x = fmaf(r00, vc.y, fmaf(r01, vc.z, fmaf(r02, vc.w, t0)));
        const float o3y = fmaf(r10, vc.y, fmaf(r11, vc.z, fmaf(r12, vc.w, t1)));
        const float o3z = fmaf(r20, vc.y, fmaf(r21, vc.z, fmaf(r22, vc.w, t2)));

        __stcs(&dst[0], make_float4(o0x, o0y, o0z, o1x));
        __stcs(&dst[1], make_float4(o1y, o1z, o2x, o2y));
        __stcs(&dst[2], make_float4(o2z, o3x, o3y, o3z));
    }
}

extern "C" void kernel_launch(void* const* d_in, const int* in_sizes, int n_in,
                              void* d_out, int out_size)
{
    const float* X    = (const float*)d_in[0];   // [B,T,N,3]
    const float* dofs = (const float*)d_in[1];   // [B,T,6]

    const int nBT = in_sizes[1] / 6;             // 1792

    se3_transform_kernel<<<nBT, THREADS>>>(X, dofs, (float*)d_out);
}

// round 11
// speedup vs baseline: 1.5682x; 1.5682x over previous
#include <cuda_runtime.h>
#include <math.h>

// SE(3) exp + point transform, single kernel, NO block barrier, NO shfl.
// out[bt,n,:] = R(dofs[bt]) * X[bt,n,:] + t(dofs[bt])
// X_v: [B,T,N,3] f32, dofs: [B,T,6] f32, out: [B,T,N,3] f32. B=64,T=28,N=4096.
//
// R6 macro-shape (proven fastest): 4 pts/thread, MLP_p1=3, 7168x256.
// This round: all lanes compute R,t redundantly with a FAST prologue
// (rsqrtf + __sinf/__cosf(theta/2) half-angle identities) — predicated-off
// lanes don't save issue slots, so lane-0+12xSHFL only added latency and
// instructions. Half-angle form avoids (1-cos) cancellation:
//   sin(th) = 2 s2 c2,  1-cos(th) = 2 s2^2.

#define THREADS 256

__global__ void __launch_bounds__(THREADS)
se3_transform_kernel(const float* __restrict__ X,
                     const float* __restrict__ dofs,
                     float* __restrict__ out)
{
    // Flat tile index (1 tile = 4 points = 12 floats). 1024 tiles per bt
    // slice; warp spans 32 consecutive tiles -> one bt per warp.
    const unsigned tile = blockIdx.x * THREADS + threadIdx.x;
    const unsigned bt   = tile >> 10;

    const size_t base = (size_t)tile * 12;       // float offset
    const float4* __restrict__ src = reinterpret_cast<const float4*>(X + base);
    float4* __restrict__ dst = reinterpret_cast<float4*>(out + base);

    // ---- issue data loads FIRST (independent of R,t) ----
    const float4 a = __ldcs(&src[0]);   // x0 y0 z0 x1
    const float4 b = __ldcs(&src[1]);   // y1 z1 x2 y2
    const float4 c = __ldcs(&src[2]);   // z2 x3 y3 z3

    // ---- fast SE(3) prologue, all lanes (hidden under load latency) ----
    const float* d = dofs + bt * 6;
    const float tx = __ldg(&d[0]), ty = __ldg(&d[1]), tz = __ldg(&d[2]);
    const float wx = __ldg(&d[3]), wy = __ldg(&d[4]), wz = __ldg(&d[5]);

    const float nrm   = wx*wx + wy*wy + wz*wz;
    const float th2c  = fmaxf(nrm, 1.0e-4f);     // clip BEFORE sqrt (matches ref)
    const float inv_t = rsqrtf(th2c);            // 1/theta
    const float theta = th2c * inv_t;            // theta = th2c / sqrt(th2c)

    const float s2 = __sinf(0.5f * theta);       // sin(theta/2), MUFU
    const float c2 = __cosf(0.5f * theta);       // cos(theta/2), MUFU
    const float st = 2.0f * s2 * c2;             // sin(theta)

    const float inv_t2 = inv_t * inv_t;
    const float f1 = st * inv_t;                 // sin/theta
    const float f2 = 2.0f * s2 * s2 * inv_t2;    // (1-cos)/theta^2 (stable)
    const float f3 = (theta - st) * inv_t2 * inv_t;

    // H2 = H@H = w w^T - (w.w) I  (raw nrm, matches ref)
    const float h2xx = wx*wx - nrm, h2yy = wy*wy - nrm, h2zz = wz*wz - nrm;
    const float h2xy = wx*wy, h2xz = wx*wz, h2yz = wy*wz;

    const float r00 = 1.0f + f2*h2xx;
    const float r01 = -f1*wz + f2*h2xy;
    const float r02 =  f1*wy + f2*h2xz;
    const float r10 =  f1*wz + f2*h2xy;
    const float r11 = 1.0f + f2*h2yy;
    const float r12 = -f1*wx + f2*h2yz;
    const float r20 = -f1*wy + f2*h2xz;
    const float r21 =  f1*wx + f2*h2yz;
    const float r22 = 1.0f + f2*h2zz;

    const float v00 = 1.0f + f3*h2xx;
    const float v01 = -f2*wz + f3*h2xy;
    const float v02 =  f2*wy + f3*h2xz;
    const float v10 =  f2*wz + f3*h2xy;
    const float v11 = 1.0f + f3*h2yy;
    const float v12 = -f2*wx + f3*h2yz;
    const float v20 = -f2*wy + f3*h2xz;
    const float v21 =  f2*wx + f3*h2yz;
    const float v22 = 1.0f + f3*h2zz;

    const float t0 = v00*tx + v01*ty + v02*tz;
    const float t1 = v10*tx + v11*ty + v12*tz;
    const float t2 = v20*tx + v21*ty + v22*tz;

    // ---- transform 4 points ----
    const float o0x = fmaf(r00, a.x, fmaf(r01, a.y, fmaf(r02, a.z, t0)));
    const float o0y = fmaf(r10, a.x, fmaf(r11, a.y, fmaf(r12, a.z, t1)));
    const float o0z = fmaf(r20, a.x, fmaf(r21, a.y, fmaf(r22, a.z, t2)));

    const float o1x = fmaf(r00, a.w, fmaf(r01, b.x, fmaf(r02, b.y, t0)));
    const float o1y = fmaf(r10, a.w, fmaf(r11, b.x, fmaf(r12, b.y, t1)));
    const float o1z = fmaf(r20, a.w, fmaf(r21, b.x, fmaf(r22, b.y, t2)));

    const float o2x = fmaf(r00, b.z, fmaf(r01, b.w, fmaf(r02, c.x, t0)));
    const float o2y = fmaf(r10, b.z, fmaf(r11, b.w, fmaf(r12, c.x, t1)));
    const float o2z = fmaf(r20, b.z, fmaf(r21, b.w, fmaf(r22, c.x, t2)));

    const float o3x = fmaf(r00, c.y, fmaf(r01, c.z, fmaf(r02, c.w, t0)));
    const float o3y = fmaf(r10, c.y, fmaf(r11, c.z, fmaf(r12, c.w, t1)));
    const float o3z = fmaf(r20, c.y, fmaf(r21, c.z, fmaf(r22, c.w, t2)));

    __stcs(&dst[0], make_float4(o0x, o0y, o0z, o1x));
    __stcs(&dst[1], make_float4(o1y, o1z, o2x, o2y));
    __stcs(&dst[2], make_float4(o2z, o3x, o3y, o3z));
}

extern "C" void kernel_launch(void* const* d_in, const int* in_sizes, int n_in,
                              void* d_out, int out_size)
{
    const float* X    = (const float*)d_in[0];   // [B,T,N,3]
    const float* dofs = (const float*)d_in[1];   // [B,T,6]

    const int nBT = in_sizes[1] / 6;             // 1792
    const int N   = (in_sizes[0] / nBT) / 3;     // 4096

    const int totalTiles = nBT * (N * 3 / 12);   // 1792 * 1024
    const int blocks = totalTiles / THREADS;     // 7168

    se3_transform_kernel<<<blocks, THREADS>>>(X, dofs, (float*)d_out);
}